// round 6
// baseline (speedup 1.0000x reference)
#include <cuda_runtime.h>

#define NN 100000
#define NE 1600000
#define NG 1000
#define NB 98              // scan blocks: 98 * 1024 >= NN

// ---------------- scratch (device globals; 16B-aligned) --------------------
__device__ __align__(16) float g_Z[NN * 64];
__device__ __align__(16) float g_Pa[NN * 64];
__device__ __align__(16) float g_Pb[NN * 64];
__device__ __align__(16) int g_deg[NN];
__device__ int g_rowstart[NN];
__device__ int g_cursor[NN];
__device__ int g_srclist[NE];
__device__ int g_bsum[128];

// compile-time buffer selection (0 = external input, 1 = g_Pa, 2 = g_Pb)
template <int SEL> __device__ __forceinline__ const float* in_buf(const float* ext);
template <> __device__ __forceinline__ const float* in_buf<0>(const float* ext) { return ext; }
template <> __device__ __forceinline__ const float* in_buf<1>(const float*) { return g_Pa; }
template <> __device__ __forceinline__ const float* in_buf<2>(const float*) { return g_Pb; }
template <int SEL> __device__ __forceinline__ float* out_buf();
template <> __device__ __forceinline__ float* out_buf<1>() { return g_Pa; }
template <> __device__ __forceinline__ float* out_buf<2>() { return g_Pb; }

// ---------------- packed f32x2 helpers (sm_103a) ---------------------------
__device__ __forceinline__ unsigned long long ffma2(
    unsigned long long a, unsigned long long b, unsigned long long c) {
    unsigned long long d;
    asm("fma.rn.f32x2 %0, %1, %2, %3;" : "=l"(d) : "l"(a), "l"(b), "l"(c));
    return d;
}
__device__ __forceinline__ unsigned long long pack2(float x) {
    unsigned long long d;
    asm("mov.b64 %0, {%1, %2};" : "=l"(d) : "f"(x), "f"(x));
    return d;
}
__device__ __forceinline__ float2 unpack2(unsigned long long v) {
    float2 r;
    asm("mov.b64 {%0, %1}, %2;" : "=f"(r.x), "=f"(r.y) : "l"(v));
    return r;
}

// ---------------- CSR build (edge_index is int32) --------------------------
__global__ void zero_deg_kernel() {
    int i = blockIdx.x * 256 + threadIdx.x;
    if (i < NN) g_deg[i] = 0;
}

// NE % 4 == 0: int4 loads, 4 atomics in flight per thread
__global__ void __launch_bounds__(256) count_deg_kernel(const int* __restrict__ ei) {
    int t = blockIdx.x * 256 + threadIdx.x;
    if (t * 4 >= NE) return;
    int4 d4 = ((const int4*)(ei + NE))[t];
    if ((unsigned)d4.x < NN) atomicAdd(&g_deg[d4.x], 1);
    if ((unsigned)d4.y < NN) atomicAdd(&g_deg[d4.y], 1);
    if ((unsigned)d4.z < NN) atomicAdd(&g_deg[d4.z], 1);
    if ((unsigned)d4.w < NN) atomicAdd(&g_deg[d4.w], 1);
}

// Phase A: per-block (1024 elems) sums
__global__ void __launch_bounds__(256) scanA_kernel() {
    __shared__ int red[256];
    int t = threadIdx.x;
    int base = blockIdx.x * 1024 + t * 4;
    int s = 0;
#pragma unroll
    for (int i = 0; i < 4; i++) {
        int idx = base + i;
        if (idx < NN) s += g_deg[idx];
    }
    red[t] = s;
    __syncthreads();
    for (int off = 128; off > 0; off >>= 1) {
        if (t < off) red[t] += red[t + off];
        __syncthreads();
    }
    if (t == 0) g_bsum[blockIdx.x] = red[0];
}

// Phase C: block offset (reduce bsum[0..bid)) + local prefix -> rowstart/cursor
__global__ void __launch_bounds__(256) scanC_kernel() {
    __shared__ int offsh[256];
    __shared__ int sh[256];
    int t = threadIdx.x;

    offsh[t] = (t < blockIdx.x) ? g_bsum[t] : 0;   // blockIdx < NB <= 128
    int base = blockIdx.x * 1024 + t * 4;
    int d[4];
    int s = 0;
#pragma unroll
    for (int i = 0; i < 4; i++) {
        int idx = base + i;
        d[i] = (idx < NN) ? g_deg[idx] : 0;
        s += d[i];
    }
    sh[t] = s;
    __syncthreads();
    // reduce offsh -> offsh[0]
    for (int off = 128; off > 0; off >>= 1) {
        if (t < off) offsh[t] += offsh[t + off];
        __syncthreads();
    }
    // inclusive scan of sh
    for (int off = 1; off < 256; off <<= 1) {
        int v = sh[t];
        int u = (t >= off) ? sh[t - off] : 0;
        __syncthreads();
        sh[t] = v + u;
        __syncthreads();
    }
    int run = offsh[0] + ((t == 0) ? 0 : sh[t - 1]);
#pragma unroll
    for (int i = 0; i < 4; i++) {
        int idx = base + i;
        if (idx < NN) {
            g_rowstart[idx] = run;
            g_cursor[idx] = run;
            run += d[i];
        }
    }
}

__global__ void __launch_bounds__(256) fill_csr_kernel(const int* __restrict__ ei) {
    int t = blockIdx.x * 256 + threadIdx.x;
    if (t * 4 >= NE) return;
    int4 s4 = ((const int4*)ei)[t];
    int4 d4 = ((const int4*)(ei + NE))[t];
    int s[4] = {s4.x, s4.y, s4.z, s4.w};
    int d[4] = {d4.x, d4.y, d4.z, d4.w};
#pragma unroll
    for (int i = 0; i < 4; i++) {
        if ((unsigned)s[i] < NN && (unsigned)d[i] < NN) {
            int pos = atomicAdd(&g_cursor[d[i]], 1);
            if ((unsigned)pos < NE) g_srclist[pos] = s[i];
        }
    }
}

// ---------------- GEMM: Z = A @ W, 2 rows/thread, packed f32x2 -------------
// Input P buffers are pre-relu'd by the gather kernel; x (layer 1) is raw.
// W staged in shared as ulonglong2 (4 packed f32 pairs per 16B); inner loop
// warp-uniform -> LDS.128 broadcasts, each feeding 4 FFMA2 (2 rows x 2 pairs).
template <int K, int IN_SEL>
__global__ void __launch_bounds__(256) gemm64x2_kernel(
    const float* ext_A, const float* __restrict__ W)
{
    __shared__ ulonglong2 Ws[K * 16];   // K rows x 64 cols (32 f32-pairs)
    for (int i = threadIdx.x; i < K * 16; i += 256)
        Ws[i] = ((const ulonglong2*)W)[i];
    __syncthreads();

    const float* A = in_buf<IN_SEL>(ext_A);
    int r0 = blockIdx.x * 512 + threadIdx.x;       // warp reads 32 consecutive rows
    int r1 = r0 + 256;
    if (r0 >= NN) return;
    bool has1 = (r1 < NN);

    unsigned long long acc0[32], acc1[32];
#pragma unroll
    for (int j = 0; j < 32; j++) { acc0[j] = 0ULL; acc1[j] = 0ULL; }

    const float4* A40 = (const float4*)(A + (long long)r0 * K);
    const float4* A41 = (const float4*)(A + (long long)(has1 ? r1 : r0) * K);

#pragma unroll 1
    for (int k4 = 0; k4 < K / 4; k4++) {
        float4 a0 = A40[k4];
        float4 a1 = A41[k4];
        const float av0[4] = {a0.x, a0.y, a0.z, a0.w};
        const float av1[4] = {a1.x, a1.y, a1.z, a1.w};
#pragma unroll
        for (int kk = 0; kk < 4; kk++) {
            unsigned long long m0 = pack2(av0[kk]);
            unsigned long long m1 = pack2(av1[kk]);
            const ulonglong2* wr = &Ws[(k4 * 4 + kk) * 16];
#pragma unroll
            for (int j4 = 0; j4 < 16; j4++) {
                ulonglong2 w = wr[j4];
                acc0[2 * j4 + 0] = ffma2(m0, w.x, acc0[2 * j4 + 0]);
                acc0[2 * j4 + 1] = ffma2(m0, w.y, acc0[2 * j4 + 1]);
                acc1[2 * j4 + 0] = ffma2(m1, w.x, acc1[2 * j4 + 0]);
                acc1[2 * j4 + 1] = ffma2(m1, w.y, acc1[2 * j4 + 1]);
            }
        }
    }

    float4* Z40 = (float4*)(g_Z + (long long)r0 * 64);
#pragma unroll
    for (int j4 = 0; j4 < 16; j4++) {
        float2 lo = unpack2(acc0[2 * j4]);
        float2 hi = unpack2(acc0[2 * j4 + 1]);
        Z40[j4] = make_float4(lo.x, lo.y, hi.x, hi.y);
    }
    if (has1) {
        float4* Z41 = (float4*)(g_Z + (long long)r1 * 64);
#pragma unroll
        for (int j4 = 0; j4 < 16; j4++) {
            float2 lo = unpack2(acc1[2 * j4]);
            float2 hi = unpack2(acc1[2 * j4 + 1]);
            Z41[j4] = make_float4(lo.x, lo.y, hi.x, hi.y);
        }
    }
}

// ---------------- gather: P[n] = relu((1+eps)*Z[n] + b + sum_in Z[src]) ----
// 16 threads per node, float4 lane each; unroll-4 keeps 4 gathers in flight.
// RELU fused: P is only ever consumed through relu (next GEMM / pool).
template <int OUT_SEL>
__global__ void __launch_bounds__(256) gather_kernel(
    const float* __restrict__ b, const float* __restrict__ epsp)
{
    int gid = blockIdx.x * 256 + threadIdx.x;
    int n = gid >> 4;
    int lane = gid & 15;
    if (n >= NN) return;

    const float4* Z4 = (const float4*)g_Z;
    float ep = 1.0f + *epsp;
    const float* bp = b + lane * 4;

    float4 z = Z4[n * 16 + lane];
    float4 acc;
    acc.x = fmaf(ep, z.x, bp[0]);
    acc.y = fmaf(ep, z.y, bp[1]);
    acc.z = fmaf(ep, z.z, bp[2]);
    acc.w = fmaf(ep, z.w, bp[3]);

    int beg = g_rowstart[n];
    int end = beg + g_deg[n];
    int k = beg;
    for (; k + 4 <= end; k += 4) {
        int s0 = g_srclist[k];
        int s1 = g_srclist[k + 1];
        int s2 = g_srclist[k + 2];
        int s3 = g_srclist[k + 3];
        float4 v0 = Z4[s0 * 16 + lane];
        float4 v1 = Z4[s1 * 16 + lane];
        float4 v2 = Z4[s2 * 16 + lane];
        float4 v3 = Z4[s3 * 16 + lane];
        acc.x += v0.x + v1.x + v2.x + v3.x;
        acc.y += v0.y + v1.y + v2.y + v3.y;
        acc.z += v0.z + v1.z + v2.z + v3.z;
        acc.w += v0.w + v1.w + v2.w + v3.w;
    }
    for (; k < end; k++) {
        int s = g_srclist[k];
        float4 v = Z4[s * 16 + lane];
        acc.x += v.x; acc.y += v.y; acc.z += v.z; acc.w += v.w;
    }

    acc.x = fmaxf(acc.x, 0.0f); acc.y = fmaxf(acc.y, 0.0f);
    acc.z = fmaxf(acc.z, 0.0f); acc.w = fmaxf(acc.w, 0.0f);

    float4* P4 = (float4*)out_buf<OUT_SEL>();
    P4[n * 16 + lane] = acc;
}

// ---------------- pool (batch sorted int32) + MLP head ---------------------
// g_Pa already holds relu'd layer-3 output.
__global__ void __launch_bounds__(64) pool_head_kernel(
    const int* __restrict__ batch,
    const float* __restrict__ Wf, const float* __restrict__ bf,
    const float* __restrict__ Wl, const float* __restrict__ bl,
    float* __restrict__ out)
{
    int g = blockIdx.x;
    int t = threadIdx.x;

    int lo = 0, hi = NN;
    while (lo < hi) { int m = (lo + hi) >> 1; if (batch[m] < g) lo = m + 1; else hi = m; }
    int beg = lo;
    lo = beg; hi = NN;
    while (lo < hi) { int m = (lo + hi) >> 1; if (batch[m] < g + 1) lo = m + 1; else hi = m; }
    int end = lo;

    float s = 0.0f;
    for (int n = beg; n < end; n++)
        s += g_Pa[(long long)n * 64 + t];
    float cnt = (float)(end - beg);
    float pooled = s / fmaxf(cnt, 1.0f);

    __shared__ float ps[64];
    __shared__ float ts[10];
    ps[t] = pooled;
    __syncthreads();

    if (t < 10) {
        float acc = bf[t];
        for (int j = 0; j < 64; j++)
            acc = fmaf(ps[j], Wf[j * 10 + t], acc);
        ts[t] = fmaxf(acc, 0.0f);
    }
    __syncthreads();

    if (t == 0) {
        float r = bl[0];
#pragma unroll
        for (int o = 0; o < 10; o++) r = fmaf(ts[o], Wl[o], r);
        out[g] = r;
    }
}

// ---------------- launch ---------------------------------------------------
extern "C" void kernel_launch(void* const* d_in, const int* in_sizes, int n_in,
                              void* d_out, int out_size)
{
    const float* x     = (const float*)d_in[0];
    const int*   ei    = (const int*)d_in[1];     // int32 (JAX x64 disabled)
    const int*   batch = (const int*)d_in[2];     // int32, sorted
    const float* W1 = (const float*)d_in[3];
    const float* b1 = (const float*)d_in[4];
    const float* W2 = (const float*)d_in[5];
    const float* b2 = (const float*)d_in[6];
    const float* W3 = (const float*)d_in[7];
    const float* b3 = (const float*)d_in[8];
    const float* Wf = (const float*)d_in[9];
    const float* bf = (const float*)d_in[10];
    const float* Wl = (const float*)d_in[11];
    const float* bl = (const float*)d_in[12];
    const float* e1 = (const float*)d_in[13];
    const float* e2 = (const float*)d_in[14];
    const float* e3 = (const float*)d_in[15];
    float* out = (float*)d_out;

    const int node_grid  = (NN + 255) / 256;           // 391
    const int gemm_grid  = (NN + 511) / 512;           // 196
    const int edge4_grid = (NE / 4 + 255) / 256;       // 1563
    const int gath_grid  = (NN * 16 + 255) / 256;      // 6250

    // CSR by destination (reused for all 3 layers)
    zero_deg_kernel<<<node_grid, 256>>>();
    count_deg_kernel<<<edge4_grid, 256>>>(ei);
    scanA_kernel<<<NB, 256>>>();
    scanC_kernel<<<NB, 256>>>();
    fill_csr_kernel<<<edge4_grid, 256>>>(ei);

    // Layer 1: Z = x@W1 ; Pa = relu((1+e1)Z + b1 + gather(Z))
    gemm64x2_kernel<128, 0><<<gemm_grid, 256>>>(x, W1);
    gather_kernel<1><<<gath_grid, 256>>>(b1, e1);

    // Layer 2: Z = Pa@W2 ; Pb = relu((1+e2)Z + b2 + gather(Z))
    gemm64x2_kernel<64, 1><<<gemm_grid, 256>>>(nullptr, W2);
    gather_kernel<2><<<gath_grid, 256>>>(b2, e2);

    // Layer 3: Z = Pb@W3 ; Pa = relu((1+e3)Z + b3 + gather(Z))
    gemm64x2_kernel<64, 2><<<gemm_grid, 256>>>(nullptr, W3);
    gather_kernel<1><<<gath_grid, 256>>>(b3, e3);

    // Mean-pool Pa per graph + head MLP
    pool_head_kernel<<<NG, 64>>>(batch, Wf, bf, Wl, bl, out);
}

// round 7
// speedup vs baseline: 1.0588x; 1.0588x over previous
#include <cuda_runtime.h>

#define NN 100000
#define NE 1600000
#define NG 1000
#define NB 98              // scan blocks: 98 * 1024 >= NN

// ---------------- scratch (device globals; 16B-aligned) --------------------
__device__ __align__(16) float g_Z[NN * 64];
__device__ __align__(16) float g_Pa[NN * 64];
__device__ __align__(16) float g_Pb[NN * 64];
__device__ __align__(16) int g_deg[NN];
__device__ int g_rowstart[NN];
__device__ int g_cursor[NN];
__device__ int g_srclist[NE];
__device__ int g_bsum[128];

// compile-time buffer selection (0 = external input, 1 = g_Pa, 2 = g_Pb)
template <int SEL> __device__ __forceinline__ const float* in_buf(const float* ext);
template <> __device__ __forceinline__ const float* in_buf<0>(const float* ext) { return ext; }
template <> __device__ __forceinline__ const float* in_buf<1>(const float*) { return g_Pa; }
template <> __device__ __forceinline__ const float* in_buf<2>(const float*) { return g_Pb; }
template <int SEL> __device__ __forceinline__ float* out_buf();
template <> __device__ __forceinline__ float* out_buf<1>() { return g_Pa; }
template <> __device__ __forceinline__ float* out_buf<2>() { return g_Pb; }

// ---------------- packed f32x2 helpers (sm_103a) ---------------------------
__device__ __forceinline__ unsigned long long ffma2(
    unsigned long long a, unsigned long long b, unsigned long long c) {
    unsigned long long d;
    asm("fma.rn.f32x2 %0, %1, %2, %3;" : "=l"(d) : "l"(a), "l"(b), "l"(c));
    return d;
}
__device__ __forceinline__ unsigned long long pack2(float x) {
    unsigned long long d;
    asm("mov.b64 %0, {%1, %2};" : "=l"(d) : "f"(x), "f"(x));
    return d;
}
__device__ __forceinline__ float2 unpack2(unsigned long long v) {
    float2 r;
    asm("mov.b64 {%0, %1}, %2;" : "=f"(r.x), "=f"(r.y) : "l"(v));
    return r;
}

// ---------------- CSR build (edge_index is int32) --------------------------
__global__ void zero_deg_kernel() {
    int i = blockIdx.x * 256 + threadIdx.x;
    if (i < NN) g_deg[i] = 0;
}

// NE % 4 == 0: int4 loads, 4 atomics in flight per thread
__global__ void __launch_bounds__(256) count_deg_kernel(const int* __restrict__ ei) {
    int t = blockIdx.x * 256 + threadIdx.x;
    if (t * 4 >= NE) return;
    int4 d4 = ((const int4*)(ei + NE))[t];
    if ((unsigned)d4.x < NN) atomicAdd(&g_deg[d4.x], 1);
    if ((unsigned)d4.y < NN) atomicAdd(&g_deg[d4.y], 1);
    if ((unsigned)d4.z < NN) atomicAdd(&g_deg[d4.z], 1);
    if ((unsigned)d4.w < NN) atomicAdd(&g_deg[d4.w], 1);
}

// Phase A: per-block (1024 elems) sums
__global__ void __launch_bounds__(256) scanA_kernel() {
    __shared__ int red[256];
    int t = threadIdx.x;
    int base = blockIdx.x * 1024 + t * 4;
    int s = 0;
#pragma unroll
    for (int i = 0; i < 4; i++) {
        int idx = base + i;
        if (idx < NN) s += g_deg[idx];
    }
    red[t] = s;
    __syncthreads();
    for (int off = 128; off > 0; off >>= 1) {
        if (t < off) red[t] += red[t + off];
        __syncthreads();
    }
    if (t == 0) g_bsum[blockIdx.x] = red[0];
}

// Phase C: block offset (reduce bsum[0..bid)) + local prefix -> rowstart/cursor
__global__ void __launch_bounds__(256) scanC_kernel() {
    __shared__ int offsh[256];
    __shared__ int sh[256];
    int t = threadIdx.x;

    offsh[t] = (t < blockIdx.x) ? g_bsum[t] : 0;   // blockIdx < NB <= 128
    int base = blockIdx.x * 1024 + t * 4;
    int d[4];
    int s = 0;
#pragma unroll
    for (int i = 0; i < 4; i++) {
        int idx = base + i;
        d[i] = (idx < NN) ? g_deg[idx] : 0;
        s += d[i];
    }
    sh[t] = s;
    __syncthreads();
    for (int off = 128; off > 0; off >>= 1) {
        if (t < off) offsh[t] += offsh[t + off];
        __syncthreads();
    }
    for (int off = 1; off < 256; off <<= 1) {
        int v = sh[t];
        int u = (t >= off) ? sh[t - off] : 0;
        __syncthreads();
        sh[t] = v + u;
        __syncthreads();
    }
    int run = offsh[0] + ((t == 0) ? 0 : sh[t - 1]);
#pragma unroll
    for (int i = 0; i < 4; i++) {
        int idx = base + i;
        if (idx < NN) {
            g_rowstart[idx] = run;
            g_cursor[idx] = run;
            run += d[i];
        }
    }
}

__global__ void __launch_bounds__(256) fill_csr_kernel(const int* __restrict__ ei) {
    int t = blockIdx.x * 256 + threadIdx.x;
    if (t * 4 >= NE) return;
    int4 s4 = ((const int4*)ei)[t];
    int4 d4 = ((const int4*)(ei + NE))[t];
    int s[4] = {s4.x, s4.y, s4.z, s4.w};
    int d[4] = {d4.x, d4.y, d4.z, d4.w};
#pragma unroll
    for (int i = 0; i < 4; i++) {
        if ((unsigned)s[i] < NN && (unsigned)d[i] < NN) {
            int pos = atomicAdd(&g_cursor[d[i]], 1);
            if ((unsigned)pos < NE) g_srclist[pos] = s[i];
        }
    }
}

// ---------------- GEMM: Z = A @ W, 1 row/thread, packed f32x2 --------------
// acc = 32 ulonglong = 64 regs (no spill). Per k-step: 16 warp-uniform
// LDS.128 + 32 FFMA2 (vs 16 LDS + 64 FFMA scalar) -> ~1.6x issue reduction.
template <int K, int IN_SEL>
__global__ void __launch_bounds__(256) gemm64x2_kernel(
    const float* ext_A, const float* __restrict__ W)
{
    __shared__ ulonglong2 Ws[K * 16];   // K rows x 64 cols (32 f32-pairs)
    for (int i = threadIdx.x; i < K * 16; i += 256)
        Ws[i] = ((const ulonglong2*)W)[i];
    __syncthreads();

    const float* A = in_buf<IN_SEL>(ext_A);
    int row = blockIdx.x * 256 + threadIdx.x;
    if (row >= NN) return;

    unsigned long long acc[32];
#pragma unroll
    for (int j = 0; j < 32; j++) acc[j] = 0ULL;

    const float4* A4 = (const float4*)(A + (long long)row * K);
#pragma unroll 1
    for (int k4 = 0; k4 < K / 4; k4++) {
        float4 a = A4[k4];
        const float av[4] = {a.x, a.y, a.z, a.w};
#pragma unroll
        for (int kk = 0; kk < 4; kk++) {
            unsigned long long m = pack2(av[kk]);
            const ulonglong2* wr = &Ws[(k4 * 4 + kk) * 16];
#pragma unroll
            for (int j4 = 0; j4 < 16; j4++) {
                ulonglong2 w = wr[j4];
                acc[2 * j4 + 0] = ffma2(m, w.x, acc[2 * j4 + 0]);
                acc[2 * j4 + 1] = ffma2(m, w.y, acc[2 * j4 + 1]);
            }
        }
    }

    float4* Z4 = (float4*)(g_Z + (long long)row * 64);
#pragma unroll
    for (int j4 = 0; j4 < 16; j4++) {
        float2 lo = unpack2(acc[2 * j4]);
        float2 hi = unpack2(acc[2 * j4 + 1]);
        Z4[j4] = make_float4(lo.x, lo.y, hi.x, hi.y);
    }
}

// ---------------- gather: P[n] = relu((1+eps)*Z[n] + b + sum_in Z[src]) ----
// 16 threads per node, float4 lane each; unroll-4 keeps 4 gathers in flight.
template <int OUT_SEL>
__global__ void __launch_bounds__(256) gather_kernel(
    const float* __restrict__ b, const float* __restrict__ epsp)
{
    int gid = blockIdx.x * 256 + threadIdx.x;
    int n = gid >> 4;
    int lane = gid & 15;
    if (n >= NN) return;

    const float4* Z4 = (const float4*)g_Z;
    float ep = 1.0f + *epsp;
    const float* bp = b + lane * 4;

    float4 z = Z4[n * 16 + lane];
    float4 acc;
    acc.x = fmaf(ep, z.x, bp[0]);
    acc.y = fmaf(ep, z.y, bp[1]);
    acc.z = fmaf(ep, z.z, bp[2]);
    acc.w = fmaf(ep, z.w, bp[3]);

    int beg = g_rowstart[n];
    int end = beg + g_deg[n];
    int k = beg;
    for (; k + 4 <= end; k += 4) {
        int s0 = g_srclist[k];
        int s1 = g_srclist[k + 1];
        int s2 = g_srclist[k + 2];
        int s3 = g_srclist[k + 3];
        float4 v0 = Z4[s0 * 16 + lane];
        float4 v1 = Z4[s1 * 16 + lane];
        float4 v2 = Z4[s2 * 16 + lane];
        float4 v3 = Z4[s3 * 16 + lane];
        acc.x += v0.x + v1.x + v2.x + v3.x;
        acc.y += v0.y + v1.y + v2.y + v3.y;
        acc.z += v0.z + v1.z + v2.z + v3.z;
        acc.w += v0.w + v1.w + v2.w + v3.w;
    }
    for (; k < end; k++) {
        int s = g_srclist[k];
        float4 v = Z4[s * 16 + lane];
        acc.x += v.x; acc.y += v.y; acc.z += v.z; acc.w += v.w;
    }

    acc.x = fmaxf(acc.x, 0.0f); acc.y = fmaxf(acc.y, 0.0f);
    acc.z = fmaxf(acc.z, 0.0f); acc.w = fmaxf(acc.w, 0.0f);

    float4* P4 = (float4*)out_buf<OUT_SEL>();
    P4[n * 16 + lane] = acc;
}

// ---------------- pool (batch sorted int32) + MLP head ---------------------
// g_Pa already holds relu'd layer-3 output.
__global__ void __launch_bounds__(64) pool_head_kernel(
    const int* __restrict__ batch,
    const float* __restrict__ Wf, const float* __restrict__ bf,
    const float* __restrict__ Wl, const float* __restrict__ bl,
    float* __restrict__ out)
{
    int g = blockIdx.x;
    int t = threadIdx.x;

    int lo = 0, hi = NN;
    while (lo < hi) { int m = (lo + hi) >> 1; if (batch[m] < g) lo = m + 1; else hi = m; }
    int beg = lo;
    lo = beg; hi = NN;
    while (lo < hi) { int m = (lo + hi) >> 1; if (batch[m] < g + 1) lo = m + 1; else hi = m; }
    int end = lo;

    float s = 0.0f;
    for (int n = beg; n < end; n++)
        s += g_Pa[(long long)n * 64 + t];
    float cnt = (float)(end - beg);
    float pooled = s / fmaxf(cnt, 1.0f);

    __shared__ float ps[64];
    __shared__ float ts[10];
    ps[t] = pooled;
    __syncthreads();

    if (t < 10) {
        float acc = bf[t];
        for (int j = 0; j < 64; j++)
            acc = fmaf(ps[j], Wf[j * 10 + t], acc);
        ts[t] = fmaxf(acc, 0.0f);
    }
    __syncthreads();

    if (t == 0) {
        float r = bl[0];
#pragma unroll
        for (int o = 0; o < 10; o++) r = fmaf(ts[o], Wl[o], r);
        out[g] = r;
    }
}

// ---------------- launch ---------------------------------------------------
extern "C" void kernel_launch(void* const* d_in, const int* in_sizes, int n_in,
                              void* d_out, int out_size)
{
    const float* x     = (const float*)d_in[0];
    const int*   ei    = (const int*)d_in[1];     // int32 (JAX x64 disabled)
    const int*   batch = (const int*)d_in[2];     // int32, sorted
    const float* W1 = (const float*)d_in[3];
    const float* b1 = (const float*)d_in[4];
    const float* W2 = (const float*)d_in[5];
    const float* b2 = (const float*)d_in[6];
    const float* W3 = (const float*)d_in[7];
    const float* b3 = (const float*)d_in[8];
    const float* Wf = (const float*)d_in[9];
    const float* bf = (const float*)d_in[10];
    const float* Wl = (const float*)d_in[11];
    const float* bl = (const float*)d_in[12];
    const float* e1 = (const float*)d_in[13];
    const float* e2 = (const float*)d_in[14];
    const float* e3 = (const float*)d_in[15];
    float* out = (float*)d_out;

    const int node_grid  = (NN + 255) / 256;           // 391
    const int edge4_grid = (NE / 4 + 255) / 256;       // 1563
    const int gath_grid  = (NN * 16 + 255) / 256;      // 6250

    // CSR by destination (reused for all 3 layers)
    zero_deg_kernel<<<node_grid, 256>>>();
    count_deg_kernel<<<edge4_grid, 256>>>(ei);
    scanA_kernel<<<NB, 256>>>();
    scanC_kernel<<<NB, 256>>>();
    fill_csr_kernel<<<edge4_grid, 256>>>(ei);

    // Layer 1: Z = x@W1 ; Pa = relu((1+e1)Z + b1 + gather(Z))
    gemm64x2_kernel<128, 0><<<node_grid, 256>>>(x, W1);
    gather_kernel<1><<<gath_grid, 256>>>(b1, e1);

    // Layer 2: Z = Pa@W2 ; Pb = relu((1+e2)Z + b2 + gather(Z))
    gemm64x2_kernel<64, 1><<<node_grid, 256>>>(nullptr, W2);
    gather_kernel<2><<<gath_grid, 256>>>(b2, e2);

    // Layer 3: Z = Pb@W3 ; Pa = relu((1+e3)Z + b3 + gather(Z))
    gemm64x2_kernel<64, 2><<<node_grid, 256>>>(nullptr, W3);
    gather_kernel<1><<<gath_grid, 256>>>(b3, e3);

    // Mean-pool Pa per graph + head MLP
    pool_head_kernel<<<NG, 64>>>(batch, Wf, bf, Wl, bl, out);
}

// round 9
// speedup vs baseline: 1.0748x; 1.0151x over previous
#include <cuda_runtime.h>
#include <cuda_fp16.h>

#define NN 100000
#define NE 1600000
#define NG 1000
#define NB 98              // scan blocks: 98 * 1024 >= NN

// ---------------- scratch (device globals; 16B-aligned) --------------------
__device__ __align__(16) float g_Z[NN * 64];
__device__ __align__(16) __half g_Z16[NN * 64];   // fp16 message copy of Z
__device__ __align__(16) float g_Pa[NN * 64];
__device__ __align__(16) float g_Pb[NN * 64];
__device__ __align__(16) int g_deg[NN];
__device__ int g_rowstart[NN];
__device__ int g_cursor[NN];
__device__ int g_srclist[NE];
__device__ int g_bsum[128];

// compile-time buffer selection (0 = external input, 1 = g_Pa, 2 = g_Pb)
template <int SEL> __device__ __forceinline__ const float* in_buf(const float* ext);
template <> __device__ __forceinline__ const float* in_buf<0>(const float* ext) { return ext; }
template <> __device__ __forceinline__ const float* in_buf<1>(const float*) { return g_Pa; }
template <> __device__ __forceinline__ const float* in_buf<2>(const float*) { return g_Pb; }
template <int SEL> __device__ __forceinline__ float* out_buf();
template <> __device__ __forceinline__ float* out_buf<1>() { return g_Pa; }
template <> __device__ __forceinline__ float* out_buf<2>() { return g_Pb; }

// ---------------- packed f32x2 helpers (sm_103a) ---------------------------
__device__ __forceinline__ unsigned long long ffma2(
    unsigned long long a, unsigned long long b, unsigned long long c) {
    unsigned long long d;
    asm("fma.rn.f32x2 %0, %1, %2, %3;" : "=l"(d) : "l"(a), "l"(b), "l"(c));
    return d;
}
__device__ __forceinline__ unsigned long long pack2(float x) {
    unsigned long long d;
    asm("mov.b64 %0, {%1, %2};" : "=l"(d) : "f"(x), "f"(x));
    return d;
}
__device__ __forceinline__ float2 unpack2(unsigned long long v) {
    float2 r;
    asm("mov.b64 {%0, %1}, %2;" : "=f"(r.x), "=f"(r.y) : "l"(v));
    return r;
}

// ---------------- half2 <-> uint bit-casts ----------------------------------
__device__ __forceinline__ unsigned h2_to_u(__half2 h) {
    __half2_raw r = *reinterpret_cast<__half2_raw*>(&h);
    return (unsigned)r.x | ((unsigned)r.y << 16);
}
__device__ __forceinline__ __half2 u_to_h2(unsigned u) {
    __half2_raw r;
    r.x = (unsigned short)(u & 0xFFFF);
    r.y = (unsigned short)(u >> 16);
    return *reinterpret_cast<__half2*>(&r);
}

// ---------------- CSR build (edge_index is int32) --------------------------
__global__ void zero_deg_kernel() {
    int i = blockIdx.x * 256 + threadIdx.x;
    if (i < NN) g_deg[i] = 0;
}

__global__ void __launch_bounds__(256) count_deg_kernel(const int* __restrict__ ei) {
    int t = blockIdx.x * 256 + threadIdx.x;
    if (t * 4 >= NE) return;
    int4 d4 = ((const int4*)(ei + NE))[t];
    if ((unsigned)d4.x < NN) atomicAdd(&g_deg[d4.x], 1);
    if ((unsigned)d4.y < NN) atomicAdd(&g_deg[d4.y], 1);
    if ((unsigned)d4.z < NN) atomicAdd(&g_deg[d4.z], 1);
    if ((unsigned)d4.w < NN) atomicAdd(&g_deg[d4.w], 1);
}

__global__ void __launch_bounds__(256) scanA_kernel() {
    __shared__ int red[256];
    int t = threadIdx.x;
    int base = blockIdx.x * 1024 + t * 4;
    int s = 0;
#pragma unroll
    for (int i = 0; i < 4; i++) {
        int idx = base + i;
        if (idx < NN) s += g_deg[idx];
    }
    red[t] = s;
    __syncthreads();
    for (int off = 128; off > 0; off >>= 1) {
        if (t < off) red[t] += red[t + off];
        __syncthreads();
    }
    if (t == 0) g_bsum[blockIdx.x] = red[0];
}

__global__ void __launch_bounds__(256) scanC_kernel() {
    __shared__ int offsh[256];
    __shared__ int sh[256];
    int t = threadIdx.x;

    offsh[t] = (t < blockIdx.x) ? g_bsum[t] : 0;
    int base = blockIdx.x * 1024 + t * 4;
    int d[4];
    int s = 0;
#pragma unroll
    for (int i = 0; i < 4; i++) {
        int idx = base + i;
        d[i] = (idx < NN) ? g_deg[idx] : 0;
        s += d[i];
    }
    sh[t] = s;
    __syncthreads();
    for (int off = 128; off > 0; off >>= 1) {
        if (t < off) offsh[t] += offsh[t + off];
        __syncthreads();
    }
    for (int off = 1; off < 256; off <<= 1) {
        int v = sh[t];
        int u = (t >= off) ? sh[t - off] : 0;
        __syncthreads();
        sh[t] = v + u;
        __syncthreads();
    }
    int run = offsh[0] + ((t == 0) ? 0 : sh[t - 1]);
#pragma unroll
    for (int i = 0; i < 4; i++) {
        int idx = base + i;
        if (idx < NN) {
            g_rowstart[idx] = run;
            g_cursor[idx] = run;
            run += d[i];
        }
    }
}

__global__ void __launch_bounds__(256) fill_csr_kernel(const int* __restrict__ ei) {
    int t = blockIdx.x * 256 + threadIdx.x;
    if (t * 4 >= NE) return;
    int4 s4 = ((const int4*)ei)[t];
    int4 d4 = ((const int4*)(ei + NE))[t];
    int s[4] = {s4.x, s4.y, s4.z, s4.w};
    int d[4] = {d4.x, d4.y, d4.z, d4.w};
#pragma unroll
    for (int i = 0; i < 4; i++) {
        if ((unsigned)s[i] < NN && (unsigned)d[i] < NN) {
            int pos = atomicAdd(&g_cursor[d[i]], 1);
            if ((unsigned)pos < NE) g_srclist[pos] = s[i];
        }
    }
}

// ---------------- GEMM: Z = A @ W (fp32) + Z16 (fp16 copy) -----------------
template <int K, int IN_SEL>
__global__ void __launch_bounds__(256) gemm64x2_kernel(
    const float* ext_A, const float* __restrict__ W)
{
    __shared__ ulonglong2 Ws[K * 16];   // K rows x 64 cols (32 f32-pairs)
    for (int i = threadIdx.x; i < K * 16; i += 256)
        Ws[i] = ((const ulonglong2*)W)[i];
    __syncthreads();

    const float* A = in_buf<IN_SEL>(ext_A);
    int row = blockIdx.x * 256 + threadIdx.x;
    if (row >= NN) return;

    unsigned long long acc[32];
#pragma unroll
    for (int j = 0; j < 32; j++) acc[j] = 0ULL;

    const float4* A4 = (const float4*)(A + (long long)row * K);
#pragma unroll 1
    for (int k4 = 0; k4 < K / 4; k4++) {
        float4 a = A4[k4];
        const float av[4] = {a.x, a.y, a.z, a.w};
#pragma unroll
        for (int kk = 0; kk < 4; kk++) {
            unsigned long long m = pack2(av[kk]);
            const ulonglong2* wr = &Ws[(k4 * 4 + kk) * 16];
#pragma unroll
            for (int j4 = 0; j4 < 16; j4++) {
                ulonglong2 w = wr[j4];
                acc[2 * j4 + 0] = ffma2(m, w.x, acc[2 * j4 + 0]);
                acc[2 * j4 + 1] = ffma2(m, w.y, acc[2 * j4 + 1]);
            }
        }
    }

    float4* Z4 = (float4*)(g_Z + (long long)row * 64);
    uint4*  H4 = (uint4*)(g_Z16 + (long long)row * 64);
#pragma unroll
    for (int j4 = 0; j4 < 16; j4++) {
        float2 lo = unpack2(acc[2 * j4]);
        float2 hi = unpack2(acc[2 * j4 + 1]);
        Z4[j4] = make_float4(lo.x, lo.y, hi.x, hi.y);
    }
#pragma unroll
    for (int j8 = 0; j8 < 8; j8++) {       // 8 halves per uint4
        float2 p0 = unpack2(acc[4 * j8 + 0]);
        float2 p1 = unpack2(acc[4 * j8 + 1]);
        float2 p2 = unpack2(acc[4 * j8 + 2]);
        float2 p3 = unpack2(acc[4 * j8 + 3]);
        uint4 h;
        h.x = h2_to_u(__float22half2_rn(p0));
        h.y = h2_to_u(__float22half2_rn(p1));
        h.z = h2_to_u(__float22half2_rn(p2));
        h.w = h2_to_u(__float22half2_rn(p3));
        H4[j8] = h;
    }
}

// ---- gather: P[n] = relu((1+eps)*Z[n](fp32) + b + sum_in Z16[src](fp16)) --
// 8 threads per node; each lane owns 8 dims (one uint4 of fp16 messages,
// two float4 of fp32 self-term). fp32 accumulation. Unroll-4 MLP.
template <int OUT_SEL>
__global__ void __launch_bounds__(256) gather_kernel(
    const float* __restrict__ b, const float* __restrict__ epsp)
{
    int gid = blockIdx.x * 256 + threadIdx.x;
    int n = gid >> 3;
    int lane = gid & 7;
    if (n >= NN) return;

    const float4* Z4 = (const float4*)g_Z;
    const uint4*  H4 = (const uint4*)g_Z16;
    float ep = 1.0f + *epsp;
    const float* bp = b + lane * 8;

    float4 z0 = Z4[n * 16 + lane * 2];
    float4 z1 = Z4[n * 16 + lane * 2 + 1];
    float a0 = fmaf(ep, z0.x, bp[0]);
    float a1 = fmaf(ep, z0.y, bp[1]);
    float a2 = fmaf(ep, z0.z, bp[2]);
    float a3 = fmaf(ep, z0.w, bp[3]);
    float a4 = fmaf(ep, z1.x, bp[4]);
    float a5 = fmaf(ep, z1.y, bp[5]);
    float a6 = fmaf(ep, z1.z, bp[6]);
    float a7 = fmaf(ep, z1.w, bp[7]);

    int beg = g_rowstart[n];
    int end = beg + g_deg[n];
    int k = beg;
    for (; k + 4 <= end; k += 4) {
        int s0 = g_srclist[k];
        int s1 = g_srclist[k + 1];
        int s2 = g_srclist[k + 2];
        int s3 = g_srclist[k + 3];
        uint4 h0 = H4[s0 * 8 + lane];
        uint4 h1 = H4[s1 * 8 + lane];
        uint4 h2 = H4[s2 * 8 + lane];
        uint4 h3 = H4[s3 * 8 + lane];
#pragma unroll
        for (int i = 0; i < 4; i++) {
            uint4 h = (i == 0) ? h0 : (i == 1) ? h1 : (i == 2) ? h2 : h3;
            float2 f0 = __half22float2(u_to_h2(h.x));
            float2 f1 = __half22float2(u_to_h2(h.y));
            float2 f2 = __half22float2(u_to_h2(h.z));
            float2 f3 = __half22float2(u_to_h2(h.w));
            a0 += f0.x; a1 += f0.y; a2 += f1.x; a3 += f1.y;
            a4 += f2.x; a5 += f2.y; a6 += f3.x; a7 += f3.y;
        }
    }
    for (; k < end; k++) {
        int s = g_srclist[k];
        uint4 h = H4[s * 8 + lane];
        float2 f0 = __half22float2(u_to_h2(h.x));
        float2 f1 = __half22float2(u_to_h2(h.y));
        float2 f2 = __half22float2(u_to_h2(h.z));
        float2 f3 = __half22float2(u_to_h2(h.w));
        a0 += f0.x; a1 += f0.y; a2 += f1.x; a3 += f1.y;
        a4 += f2.x; a5 += f2.y; a6 += f3.x; a7 += f3.y;
    }

    float4* P4 = (float4*)out_buf<OUT_SEL>();
    P4[n * 16 + lane * 2] = make_float4(fmaxf(a0, 0.0f), fmaxf(a1, 0.0f),
                                        fmaxf(a2, 0.0f), fmaxf(a3, 0.0f));
    P4[n * 16 + lane * 2 + 1] = make_float4(fmaxf(a4, 0.0f), fmaxf(a5, 0.0f),
                                            fmaxf(a6, 0.0f), fmaxf(a7, 0.0f));
}

// ---------------- pool (batch sorted int32) + MLP head ---------------------
__global__ void __launch_bounds__(64) pool_head_kernel(
    const int* __restrict__ batch,
    const float* __restrict__ Wf, const float* __restrict__ bf,
    const float* __restrict__ Wl, const float* __restrict__ bl,
    float* __restrict__ out)
{
    int g = blockIdx.x;
    int t = threadIdx.x;

    int lo = 0, hi = NN;
    while (lo < hi) { int m = (lo + hi) >> 1; if (batch[m] < g) lo = m + 1; else hi = m; }
    int beg = lo;
    lo = beg; hi = NN;
    while (lo < hi) { int m = (lo + hi) >> 1; if (batch[m] < g + 1) lo = m + 1; else hi = m; }
    int end = lo;

    float s = 0.0f;
    for (int n = beg; n < end; n++)
        s += g_Pa[(long long)n * 64 + t];
    float cnt = (float)(end - beg);
    float pooled = s / fmaxf(cnt, 1.0f);

    __shared__ float ps[64];
    __shared__ float ts[10];
    ps[t] = pooled;
    __syncthreads();

    if (t < 10) {
        float acc = bf[t];
        for (int j = 0; j < 64; j++)
            acc = fmaf(ps[j], Wf[j * 10 + t], acc);
        ts[t] = fmaxf(acc, 0.0f);
    }
    __syncthreads();

    if (t == 0) {
        float r = bl[0];
#pragma unroll
        for (int o = 0; o < 10; o++) r = fmaf(ts[o], Wl[o], r);
        out[g] = r;
    }
}

// ---------------- launch ---------------------------------------------------
extern "C" void kernel_launch(void* const* d_in, const int* in_sizes, int n_in,
                              void* d_out, int out_size)
{
    const float* x     = (const float*)d_in[0];
    const int*   ei    = (const int*)d_in[1];     // int32 (JAX x64 disabled)
    const int*   batch = (const int*)d_in[2];     // int32, sorted
    const float* W1 = (const float*)d_in[3];
    const float* b1 = (const float*)d_in[4];
    const float* W2 = (const float*)d_in[5];
    const float* b2 = (const float*)d_in[6];
    const float* W3 = (const float*)d_in[7];
    const float* b3 = (const float*)d_in[8];
    const float* Wf = (const float*)d_in[9];
    const float* bf = (const float*)d_in[10];
    const float* Wl = (const float*)d_in[11];
    const float* bl = (const float*)d_in[12];
    const float* e1 = (const float*)d_in[13];
    const float* e2 = (const float*)d_in[14];
    const float* e3 = (const float*)d_in[15];
    float* out = (float*)d_out;

    const int node_grid  = (NN + 255) / 256;           // 391
    const int edge4_grid = (NE / 4 + 255) / 256;       // 1563
    const int gath_grid  = (NN * 8 + 255) / 256;       // 3125

    // CSR by destination (reused for all 3 layers)
    zero_deg_kernel<<<node_grid, 256>>>();
    count_deg_kernel<<<edge4_grid, 256>>>(ei);
    scanA_kernel<<<NB, 256>>>();
    scanC_kernel<<<NB, 256>>>();
    fill_csr_kernel<<<edge4_grid, 256>>>(ei);

    // Layer 1: Z = x@W1 ; Pa = relu((1+e1)Z + b1 + gather16(Z))
    gemm64x2_kernel<128, 0><<<node_grid, 256>>>(x, W1);
    gather_kernel<1><<<gath_grid, 256>>>(b1, e1);

    // Layer 2: Z = Pa@W2 ; Pb = relu((1+e2)Z + b2 + gather16(Z))
    gemm64x2_kernel<64, 1><<<node_grid, 256>>>(nullptr, W2);
    gather_kernel<2><<<gath_grid, 256>>>(b2, e2);

    // Layer 3: Z = Pb@W3 ; Pa = relu((1+e3)Z + b3 + gather16(Z))
    gemm64x2_kernel<64, 2><<<node_grid, 256>>>(nullptr, W3);
    gather_kernel<1><<<gath_grid, 256>>>(b3, e3);

    // Mean-pool Pa per graph + head MLP
    pool_head_kernel<<<NG, 64>>>(batch, Wf, bf, Wl, bl, out);
}